// round 11
// baseline (speedup 1.0000x reference)
#include <cuda_runtime.h>
#include <cuda_fp16.h>
#include <cstdint>

#define BB   16
#define NN   1024
#define DIMM 128
#define HH   8
#define DD   16
#define QSC  (0.08838834764831845f * 1.4426950408889634f)
#define XE   (BB * NN * DIMM)   // 2097152

typedef unsigned long long u64;
typedef unsigned int u32;
typedef __half h16;

// ---------------- pre-split scratch (no cudaMalloc allowed) ----------------
__device__ __align__(16) h16 g_xhi[XE],  g_xlo[XE];
__device__ __align__(16) h16 g_wqhi[DIMM * 384], g_wqlo[DIMM * 384];
__device__ __align__(16) h16 g_wohi[DIMM * DIMM], g_wolo[DIMM * DIMM];
__device__ __align__(16) h16 g_q[XE];                 // single fp16, QSC*log2e folded
__device__ __align__(16) h16 g_k[XE];                 // single fp16
__device__ __align__(16) h16 g_vhi[XE],  g_vlo[XE];
__device__ __align__(16) h16 g_aohi[XE], g_aolo[XE];

// ---------------------------- helpers --------------------------------------
__device__ __forceinline__ u32 smem_u32(const void* p) {
    u32 a;
    asm("{ .reg .u64 t; cvta.to.shared.u64 t, %1; cvt.u32.u64 %0, t; }"
        : "=r"(a) : "l"(p));
    return a;
}
__device__ __forceinline__ void mma16816(float& d0, float& d1, float& d2, float& d3,
                                         u32 a0, u32 a1, u32 a2, u32 a3,
                                         u32 b0, u32 b1) {
    asm volatile(
        "mma.sync.aligned.m16n8k16.row.col.f32.f16.f16.f32 "
        "{%0,%1,%2,%3}, {%4,%5,%6,%7}, {%8,%9}, {%0,%1,%2,%3};"
        : "+f"(d0), "+f"(d1), "+f"(d2), "+f"(d3)
        : "r"(a0), "r"(a1), "r"(a2), "r"(a3), "r"(b0), "r"(b1));
}
__device__ __forceinline__ void ldm_x4(u32* r, u32 addr) {
    asm volatile("ldmatrix.sync.aligned.m8n8.x4.shared.b16 {%0,%1,%2,%3}, [%4];"
                 : "=r"(r[0]), "=r"(r[1]), "=r"(r[2]), "=r"(r[3])
                 : "r"(addr) : "memory");
}
__device__ __forceinline__ void ldm_x2(u32* r, u32 addr) {
    asm volatile("ldmatrix.sync.aligned.m8n8.x2.shared.b16 {%0,%1}, [%2];"
                 : "=r"(r[0]), "=r"(r[1])
                 : "r"(addr) : "memory");
}
__device__ __forceinline__ void ldm_x4t(u32* r, u32 addr) {
    asm volatile("ldmatrix.sync.aligned.m8n8.x4.trans.shared.b16 {%0,%1,%2,%3}, [%4];"
                 : "=r"(r[0]), "=r"(r[1]), "=r"(r[2]), "=r"(r[3])
                 : "r"(addr) : "memory");
}
__device__ __forceinline__ float ex2f(float x) {
    float r; asm("ex2.approx.f32 %0, %1;" : "=f"(r) : "f"(x));
    return r;
}
// pack two fp32 -> f16x2 (e0 in low half), saturating to max finite
__device__ __forceinline__ u32 cvt2h(float e1, float e0) {
    u32 r; asm("cvt.rn.satfinite.f16x2.f32 %0, %1, %2;" : "=r"(r) : "f"(e1), "f"(e0));
    return r;
}
// split two fp32 into packed hi/lo f16x2
__device__ __forceinline__ void split2h(float a0, float a1, u32& hp, u32& lp) {
    hp = cvt2h(a1, a0);
    __half2 h = *(__half2*)&hp;
    lp = cvt2h(a1 - __high2float(h), a0 - __low2float(h));
}
__device__ __forceinline__ void cpa16(u32 dst, const void* src) {
    asm volatile("cp.async.cg.shared.global [%0], [%1], 16;"
                 :: "r"(dst), "l"(src) : "memory");
}
#define CP_COMMIT() asm volatile("cp.async.commit_group;" ::: "memory")
#define CP_WAIT(n)  asm volatile("cp.async.wait_group %0;" :: "n"(n) : "memory")

// ===========================================================================
// Prep: split fp32 inputs into hi/lo f16 (QSC folded into q-columns of Wqkv)
// ===========================================================================
__global__ __launch_bounds__(256)
void prep_kernel(const float* __restrict__ x, const float* __restrict__ Wqkv,
                 const float* __restrict__ Wout)
{
    const int stride = gridDim.x * blockDim.x;
    const int t0 = blockIdx.x * blockDim.x + threadIdx.x;

    for (int i = t0; i < XE / 2; i += stride) {
        float2 v = ((const float2*)x)[i];
        u32 hp, lp; split2h(v.x, v.y, hp, lp);
        ((u32*)g_xhi)[i] = hp; ((u32*)g_xlo)[i] = lp;
    }
    for (int i = t0; i < DIMM * 384 / 2; i += stride) {
        float2 v = ((const float2*)Wqkv)[i];
        if (((2 * i) % 384) < 128) { v.x *= QSC; v.y *= QSC; }
        u32 hp, lp; split2h(v.x, v.y, hp, lp);
        ((u32*)g_wqhi)[i] = hp; ((u32*)g_wqlo)[i] = lp;
    }
    for (int i = t0; i < DIMM * DIMM / 2; i += stride) {
        float2 v = ((const float2*)Wout)[i];
        u32 hp, lp; split2h(v.x, v.y, hp, lp);
        ((u32*)g_wohi)[i] = hp; ((u32*)g_wolo)[i] = lp;
    }
}

// ===========================================================================
// fp16x3 warp-MMA GEMM, cp.async double-buffered.
// CTA tile 64x128, 8 warps as 4(m)x2(n), warp tile m16xn64, K chunks of 32.
// ===========================================================================
struct GemmSmem {
    __align__(16) h16 Ahi[2][64][40];    // 80B row stride
    __align__(16) h16 Alo[2][64][40];
    __align__(16) h16 Bhi[2][32][136];   // 272B row stride
    __align__(16) h16 Blo[2][32][136];
};

__device__ __forceinline__ void gemm_issue(
    GemmSmem* s, int buf,
    const h16* gAhi, const h16* gAlo, const h16* gBhi, const h16* gBlo,
    int Nn, int rowBase, int colBase, int kb, int tid)
{
    {
        int r = tid >> 2, c = (tid & 3) * 8;          // 64 rows x 4 vec8
        size_t so = (size_t)(rowBase + r) * DIMM + kb * 32 + c;
        cpa16(smem_u32(&s->Ahi[buf][r][c]), gAhi + so);
        cpa16(smem_u32(&s->Alo[buf][r][c]), gAlo + so);
    }
    #pragma unroll
    for (int it = 0; it < 2; it++) {
        int idx = tid + it * 256;
        int r = idx >> 4, c = (idx & 15) * 8;         // 32 rows x 16 vec8
        size_t so = (size_t)(kb * 32 + r) * Nn + colBase + c;
        cpa16(smem_u32(&s->Bhi[buf][r][c]), gBhi + so);
        cpa16(smem_u32(&s->Blo[buf][r][c]), gBlo + so);
    }
}

__device__ __forceinline__ void gemm_compute(
    GemmSmem* s, int buf, int lane, int wm, int wn, float acc[8][4])
{
    #pragma unroll
    for (int ks = 0; ks < 2; ks++) {
        u32 ah[4], al[4];
        u32 ahb = smem_u32(&s->Ahi[buf][wm * 16 + (lane & 15)][ks * 16 + (lane >> 4) * 8]);
        u32 alb = smem_u32(&s->Alo[buf][wm * 16 + (lane & 15)][ks * 16 + (lane >> 4) * 8]);
        ldm_x4(ah, ahb);
        ldm_x4(al, alb);
        u32 bhb = smem_u32(&s->Bhi[buf][ks * 16 + (lane & 15)][wn * 64 + (lane >> 4) * 8]);
        u32 blb = smem_u32(&s->Blo[buf][ks * 16 + (lane & 15)][wn * 64 + (lane >> 4) * 8]);
        #pragma unroll
        for (int np = 0; np < 4; np++) {       // two n-tiles per x4t
            u32 bh[4], bl[4];
            ldm_x4t(bh, bhb + np * 32);
            ldm_x4t(bl, blb + np * 32);
            #pragma unroll
            for (int half = 0; half < 2; half++) {
                int nt = np * 2 + half;
                u32 b0h = bh[half * 2], b1h = bh[half * 2 + 1];
                u32 b0l = bl[half * 2], b1l = bl[half * 2 + 1];
                mma16816(acc[nt][0], acc[nt][1], acc[nt][2], acc[nt][3],
                         ah[0], ah[1], ah[2], ah[3], b0h, b1h);
                mma16816(acc[nt][0], acc[nt][1], acc[nt][2], acc[nt][3],
                         ah[0], ah[1], ah[2], ah[3], b0l, b1l);
                mma16816(acc[nt][0], acc[nt][1], acc[nt][2], acc[nt][3],
                         al[0], al[1], al[2], al[3], b0h, b1h);
            }
        }
    }
}

__device__ __forceinline__ void gemm_run(
    GemmSmem* s, const h16* gAhi, const h16* gAlo,
    const h16* gBhi, const h16* gBlo,
    int Nn, int rowBase, int colBase, int tid, int lane, int wm, int wn,
    float acc[8][4])
{
    gemm_issue(s, 0, gAhi, gAlo, gBhi, gBlo, Nn, rowBase, colBase, 0, tid);
    CP_COMMIT();
    for (int kb = 0; kb < 4; kb++) {
        if (kb < 3) {
            gemm_issue(s, (kb + 1) & 1, gAhi, gAlo, gBhi, gBlo,
                       Nn, rowBase, colBase, kb + 1, tid);
            CP_COMMIT();
            CP_WAIT(1);
        } else {
            CP_WAIT(0);
        }
        __syncthreads();
        gemm_compute(s, kb & 1, lane, wm, wn, acc);
        __syncthreads();
    }
}

// GEMM1: qkv = x @ Wqkv; q,k -> single fp16; v -> split hi/lo
__global__ __launch_bounds__(256)
void gemm1_kernel()
{
    extern __shared__ char smraw[];
    GemmSmem* s = (GemmSmem*)smraw;
    const int tid = threadIdx.x, lane = tid & 31, w = tid >> 5;
    const int wm = w >> 1, wn = w & 1;
    const int rowBase = blockIdx.y * 64;
    const int cb = blockIdx.x;             // 0=q, 1=k, 2=v

    float acc[8][4] = {};
    gemm_run(s, g_xhi, g_xlo, g_wqhi, g_wqlo, 384, rowBase, cb * 128,
             tid, lane, wm, wn, acc);

    const int gid = lane >> 2, q4 = lane & 3;
    const int r0 = rowBase + wm * 16 + gid;
    if (cb < 2) {
        h16* dq = cb ? g_k : g_q;
        #pragma unroll
        for (int nt = 0; nt < 8; nt++) {
            int cc = wn * 64 + nt * 8 + q4 * 2;
            *(u32*)&dq[(size_t)r0 * DIMM + cc]       = cvt2h(acc[nt][1], acc[nt][0]);
            *(u32*)&dq[(size_t)(r0 + 8) * DIMM + cc] = cvt2h(acc[nt][3], acc[nt][2]);
        }
    } else {
        #pragma unroll
        for (int nt = 0; nt < 8; nt++) {
            int cc = wn * 64 + nt * 8 + q4 * 2;
            u32 hp, lp;
            split2h(acc[nt][0], acc[nt][1], hp, lp);
            *(u32*)&g_vhi[(size_t)r0 * DIMM + cc] = hp;
            *(u32*)&g_vlo[(size_t)r0 * DIMM + cc] = lp;
            split2h(acc[nt][2], acc[nt][3], hp, lp);
            *(u32*)&g_vhi[(size_t)(r0 + 8) * DIMM + cc] = hp;
            *(u32*)&g_vlo[(size_t)(r0 + 8) * DIMM + cc] = lp;
        }
    }
}

// GEMM2: out = ao @ Wout + bout (fp32 epilogue)
__global__ __launch_bounds__(256)
void gemm2_kernel(const float* __restrict__ bias, float* __restrict__ out)
{
    extern __shared__ char smraw[];
    GemmSmem* s = (GemmSmem*)smraw;
    const int tid = threadIdx.x, lane = tid & 31, w = tid >> 5;
    const int wm = w >> 1, wn = w & 1;
    const int rowBase = blockIdx.y * 64;

    float acc[8][4] = {};
    gemm_run(s, g_aohi, g_aolo, g_wohi, g_wolo, 128, rowBase, 0,
             tid, lane, wm, wn, acc);

    const int gid = lane >> 2, q4 = lane & 3;
    const int r0 = rowBase + wm * 16 + gid;
    #pragma unroll
    for (int nt = 0; nt < 8; nt++) {
        int cc = wn * 64 + nt * 8 + q4 * 2;
        float2 bv = *(const float2*)&bias[cc];
        *(float2*)&out[(size_t)r0 * DIMM + cc] =
            make_float2(acc[nt][0] + bv.x, acc[nt][1] + bv.y);
        *(float2*)&out[(size_t)(r0 + 8) * DIMM + cc] =
            make_float2(acc[nt][2] + bv.x, acc[nt][3] + bv.y);
    }
}

// ===========================================================================
// Warp-MMA flash attention: single-fp16 S and P, fp16x2 V.
// cp.async double-buffered K/V. klog C-init masking. Split PV accumulators.
// ===========================================================================
struct AttnSmem {
    __align__(16) h16 QT[128][24];        // 48B stride
    __align__(16) h16 KT[2][128][24];
    __align__(16) h16 VHI[2][128][24];
    __align__(16) h16 VLO[2][128][24];
    float klog[NN];
};

__device__ __forceinline__ void attn_issue(AttnSmem* s, int buf, int j0,
                                           int b, int h, int tid)
{
    int r = tid >> 1, c8 = (tid & 1) * 8;      // 128 rows x 2 vec8
    size_t src = (size_t)(b * NN + j0 + r) * DIMM + h * DD + c8;
    cpa16(smem_u32(&s->KT [buf][r][c8]), g_k   + src);
    cpa16(smem_u32(&s->VHI[buf][r][c8]), g_vhi + src);
    cpa16(smem_u32(&s->VLO[buf][r][c8]), g_vlo + src);
}

__global__ __launch_bounds__(256, 2)
void attn_mma_kernel(const float* __restrict__ mask,   // [N-1]
                     const float* __restrict__ maps)   // [B, N-1]
{
    extern __shared__ char smraw[];
    AttnSmem* s = (AttnSmem*)smraw;

    const int tid  = threadIdx.x;
    const int lane = tid & 31;
    const int w    = tid >> 5;
    const int bx   = blockIdx.x;
    const int b    = bx >> 6;
    const int h    = (bx >> 3) & 7;
    const int mt   = bx & 7;
    const int qrow0 = b * NN + mt * 128;
    const float NEGINF = __int_as_float(0xff800000);

    // Q staging + KV block 0 in group 0
    {
        int r = tid >> 1, c8 = (tid & 1) * 8;
        cpa16(smem_u32(&s->QT[r][c8]),
              g_q + (size_t)(qrow0 + r) * DIMM + h * DD + c8);
    }
    attn_issue(s, 0, 0, b, h, tid);
    CP_COMMIT();

    // klog[j] = 0 if kept else -inf
    for (int j = tid; j < NN; j += 256) {
        bool kp = (j == 0) ||
                  (mask[j - 1] != 0.0f && maps[b * (NN - 1) + j - 1] != 0.0f);
        s->klog[j] = kp ? 0.0f : NEGINF;
    }

    const u32 kb0  = smem_u32(&s->KT [0][lane & 7 ][((lane >> 3) & 1) * 8]);
    const u32 vhb0 = smem_u32(&s->VHI[0][lane & 15][(lane >> 4) * 8]);
    const u32 vlb0 = smem_u32(&s->VLO[0][lane & 15][(lane >> 4) * 8]);

    u32 qh[4];
    float oA[2][4] = {}, oB[2][4] = {};
    float lsum0 = 0.0f, lsum1 = 0.0f;

    for (int kb = 0; kb < 8; kb++) {
        if (kb < 7) {
            attn_issue(s, (kb + 1) & 1, (kb + 1) * 128, b, h, tid);
            CP_COMMIT();
            CP_WAIT(1);
        } else {
            CP_WAIT(0);
        }
        __syncthreads();

        if (kb == 0) {
            ldm_x4(qh, smem_u32(&s->QT[w * 16 + (lane & 15)][(lane >> 4) * 8]));
        }

        const int buf = kb & 1;
        const u32 kbase  = kb0  + buf * 6144;
        const u32 vhbase = vhb0 + buf * 6144;
        const u32 vlbase = vlb0 + buf * 6144;
        const int j0 = kb * 128;

        // ---- S = Q.K^T (single MMA) with klog C-init; P -> fp16 ----
        u32 phi[32];
        #pragma unroll
        for (int nt = 0; nt < 16; nt++) {
            u32 kf[2];
            ldm_x2(kf, kbase + nt * 8 * 48);
            float2 kl = *(const float2*)&s->klog[j0 + nt * 8 + (lane & 3) * 2];
            float c0 = kl.x, c1 = kl.y, c2 = kl.x, c3 = kl.y;
            mma16816(c0, c1, c2, c3, qh[0], qh[1], qh[2], qh[3], kf[0], kf[1]);

            float p0 = ex2f(c0), p1 = ex2f(c1), p2 = ex2f(c2), p3 = ex2f(c3);
            lsum0 += p0 + p1;
            lsum1 += p2 + p3;
            phi[nt * 2]     = cvt2h(p1, p0);
            phi[nt * 2 + 1] = cvt2h(p3, p2);
        }

        // ---- O += P.Vhi (oA) + P.Vlo (oB), both n-tiles per x4t ----
        #pragma unroll
        for (int t = 0; t < 8; t++) {
            const u32 vrow = t * 16 * 48;
            u32 vh[4], vl[4];
            ldm_x4t(vh, vhbase + vrow);
            ldm_x4t(vl, vlbase + vrow);
            #pragma unroll
            for (int nt = 0; nt < 2; nt++) {
                mma16816(oA[nt][0], oA[nt][1], oA[nt][2], oA[nt][3],
                         phi[4 * t], phi[4 * t + 1], phi[4 * t + 2], phi[4 * t + 3],
                         vh[nt * 2], vh[nt * 2 + 1]);
                mma16816(oB[nt][0], oB[nt][1], oB[nt][2], oB[nt][3],
                         phi[4 * t], phi[4 * t + 1], phi[4 * t + 2], phi[4 * t + 3],
                         vl[nt * 2], vl[nt * 2 + 1]);
            }
        }
        __syncthreads();
    }

    // ---- reduce l within quads, normalize, write split ao ----
    lsum0 += __shfl_xor_sync(0xffffffffu, lsum0, 1);
    lsum0 += __shfl_xor_sync(0xffffffffu, lsum0, 2);
    lsum1 += __shfl_xor_sync(0xffffffffu, lsum1, 1);
    lsum1 += __shfl_xor_sync(0xffffffffu, lsum1, 2);
    const float inv0 = 1.0f / lsum0;
    const float inv1 = 1.0f / lsum1;

    const int gid  = lane >> 2;
    const int tid4 = lane & 3;
    size_t row0 = (size_t)(qrow0 + w * 16 + gid) * DIMM + h * DD;
    size_t row1 = row0 + 8 * DIMM;
    #pragma unroll
    for (int nt = 0; nt < 2; nt++) {
        int cc = nt * 8 + tid4 * 2;
        u32 hp, lp;
        split2h((oA[nt][0] + oB[nt][0]) * inv0,
                (oA[nt][1] + oB[nt][1]) * inv0, hp, lp);
        *(u32*)&g_aohi[row0 + cc] = hp;
        *(u32*)&g_aolo[row0 + cc] = lp;
        split2h((oA[nt][2] + oB[nt][2]) * inv1,
                (oA[nt][3] + oB[nt][3]) * inv1, hp, lp);
        *(u32*)&g_aohi[row1 + cc] = hp;
        *(u32*)&g_aolo[row1 + cc] = lp;
    }
}

// ---------------------------------------------------------------------------

extern "C" void kernel_launch(void* const* d_in, const int* in_sizes, int n_in,
                              void* d_out, int out_size)
{
    const float* x    = (const float*)d_in[0];
    const float* mask = (const float*)d_in[1];
    const float* maps = (const float*)d_in[2];
    const float* Wqkv = (const float*)d_in[3];
    const float* Wout = (const float*)d_in[4];
    const float* bout = (const float*)d_in[5];
    float* out = (float*)d_out;

    static bool attr_set = false;
    if (!attr_set) {
        cudaFuncSetAttribute(gemm1_kernel,
            cudaFuncAttributeMaxDynamicSharedMemorySize, (int)sizeof(GemmSmem));
        cudaFuncSetAttribute(gemm2_kernel,
            cudaFuncAttributeMaxDynamicSharedMemorySize, (int)sizeof(GemmSmem));
        cudaFuncSetAttribute(attn_mma_kernel,
            cudaFuncAttributeMaxDynamicSharedMemorySize, (int)sizeof(AttnSmem));
        attr_set = true;
    }

    // 0) split inputs into hi/lo f16 (QSC folded into q-cols of Wqkv)
    prep_kernel<<<1024, 256>>>(x, Wqkv, Wout);

    // 1) qkv = x @ Wqkv  (q,k single fp16; v split)
    gemm1_kernel<<<dim3(3, 256), 256, sizeof(GemmSmem)>>>();

    // 2) warp-MMA flash attention (split ao epilogue)
    attn_mma_kernel<<<BB * HH * 8, 256, sizeof(AttnSmem)>>>(mask, maps);

    // 3) out = ao @ Wout + bout
    gemm2_kernel<<<dim3(1, 256), 256, sizeof(GemmSmem)>>>(bout, out);
}

// round 12
// speedup vs baseline: 1.5160x; 1.5160x over previous
#include <cuda_runtime.h>
#include <cuda_fp16.h>
#include <cstdint>

#define BB   16
#define NN   1024
#define DIMM 128
#define HH   8
#define DD   16
#define QSC  (0.08838834764831845f * 1.4426950408889634f)
#define XE   (BB * NN * DIMM)   // 2097152

typedef unsigned long long u64;
typedef unsigned int u32;
typedef __half h16;

// ---------------- pre-split scratch (no cudaMalloc allowed) ----------------
__device__ __align__(16) h16 g_xhi[XE],  g_xlo[XE];
__device__ __align__(16) h16 g_wqhi[DIMM * 384], g_wqlo[DIMM * 384];
__device__ __align__(16) h16 g_wohi[DIMM * DIMM], g_wolo[DIMM * DIMM];
__device__ __align__(16) h16 g_q[XE];                 // single fp16, QSC*log2e folded
__device__ __align__(16) h16 g_k[XE];                 // single fp16
__device__ __align__(16) h16 g_vhi[XE],  g_vlo[XE];
__device__ __align__(16) h16 g_aohi[XE], g_aolo[XE];

// ---------------------------- helpers --------------------------------------
__device__ __forceinline__ u32 smem_u32(const void* p) {
    u32 a;
    asm("{ .reg .u64 t; cvta.to.shared.u64 t, %1; cvt.u32.u64 %0, t; }"
        : "=r"(a) : "l"(p));
    return a;
}
__device__ __forceinline__ void mma16816(float& d0, float& d1, float& d2, float& d3,
                                         u32 a0, u32 a1, u32 a2, u32 a3,
                                         u32 b0, u32 b1) {
    asm volatile(
        "mma.sync.aligned.m16n8k16.row.col.f32.f16.f16.f32 "
        "{%0,%1,%2,%3}, {%4,%5,%6,%7}, {%8,%9}, {%0,%1,%2,%3};"
        : "+f"(d0), "+f"(d1), "+f"(d2), "+f"(d3)
        : "r"(a0), "r"(a1), "r"(a2), "r"(a3), "r"(b0), "r"(b1));
}
__device__ __forceinline__ void ldm_x4(u32* r, u32 addr) {
    asm volatile("ldmatrix.sync.aligned.m8n8.x4.shared.b16 {%0,%1,%2,%3}, [%4];"
                 : "=r"(r[0]), "=r"(r[1]), "=r"(r[2]), "=r"(r[3])
                 : "r"(addr) : "memory");
}
__device__ __forceinline__ void ldm_x2(u32* r, u32 addr) {
    asm volatile("ldmatrix.sync.aligned.m8n8.x2.shared.b16 {%0,%1}, [%2];"
                 : "=r"(r[0]), "=r"(r[1])
                 : "r"(addr) : "memory");
}
__device__ __forceinline__ void ldm_x4t(u32* r, u32 addr) {
    asm volatile("ldmatrix.sync.aligned.m8n8.x4.trans.shared.b16 {%0,%1,%2,%3}, [%4];"
                 : "=r"(r[0]), "=r"(r[1]), "=r"(r[2]), "=r"(r[3])
                 : "r"(addr) : "memory");
}
__device__ __forceinline__ float ex2f(float x) {
    float r; asm("ex2.approx.f32 %0, %1;" : "=f"(r) : "f"(x));
    return r;
}
// pack two fp32 -> f16x2 (e0 in low half), saturating to max finite
__device__ __forceinline__ u32 cvt2h(float e1, float e0) {
    u32 r; asm("cvt.rn.satfinite.f16x2.f32 %0, %1, %2;" : "=r"(r) : "f"(e1), "f"(e0));
    return r;
}
// split two fp32 into packed hi/lo f16x2
__device__ __forceinline__ void split2h(float a0, float a1, u32& hp, u32& lp) {
    hp = cvt2h(a1, a0);
    __half2 h = *(__half2*)&hp;
    lp = cvt2h(a1 - __high2float(h), a0 - __low2float(h));
}
__device__ __forceinline__ void cpa16(u32 dst, const void* src) {
    asm volatile("cp.async.cg.shared.global [%0], [%1], 16;"
                 :: "r"(dst), "l"(src) : "memory");
}
#define CP_COMMIT() asm volatile("cp.async.commit_group;" ::: "memory")
#define CP_WAIT(n)  asm volatile("cp.async.wait_group %0;" :: "n"(n) : "memory")

// ===========================================================================
// Prep: split fp32 inputs into hi/lo f16 (QSC folded into q-columns of Wqkv)
// ===========================================================================
__global__ __launch_bounds__(256)
void prep_kernel(const float* __restrict__ x, const float* __restrict__ Wqkv,
                 const float* __restrict__ Wout)
{
    const int stride = gridDim.x * blockDim.x;
    const int t0 = blockIdx.x * blockDim.x + threadIdx.x;

    for (int i = t0; i < XE / 2; i += stride) {
        float2 v = ((const float2*)x)[i];
        u32 hp, lp; split2h(v.x, v.y, hp, lp);
        ((u32*)g_xhi)[i] = hp; ((u32*)g_xlo)[i] = lp;
    }
    for (int i = t0; i < DIMM * 384 / 2; i += stride) {
        float2 v = ((const float2*)Wqkv)[i];
        if (((2 * i) % 384) < 128) { v.x *= QSC; v.y *= QSC; }
        u32 hp, lp; split2h(v.x, v.y, hp, lp);
        ((u32*)g_wqhi)[i] = hp; ((u32*)g_wqlo)[i] = lp;
    }
    for (int i = t0; i < DIMM * DIMM / 2; i += stride) {
        float2 v = ((const float2*)Wout)[i];
        u32 hp, lp; split2h(v.x, v.y, hp, lp);
        ((u32*)g_wohi)[i] = hp; ((u32*)g_wolo)[i] = lp;
    }
}

// ===========================================================================
// fp16x3 warp-MMA GEMM, cp.async double-buffered (R10 shape).
// CTA tile 128x128, 8 warps as 4(m)x2(n), warp tile m32xn64, K chunks of 32.
// ===========================================================================
struct GemmSmem {
    __align__(16) h16 Ahi[2][128][40];   // 80B row stride
    __align__(16) h16 Alo[2][128][40];
    __align__(16) h16 Bhi[2][32][136];   // 272B row stride
    __align__(16) h16 Blo[2][32][136];
};

__device__ __forceinline__ void gemm_issue(
    GemmSmem* s, int buf,
    const h16* gAhi, const h16* gAlo, const h16* gBhi, const h16* gBlo,
    int Nn, int rowBase, int colBase, int kb, int tid)
{
    #pragma unroll
    for (int it = 0; it < 2; it++) {
        int idx = tid + it * 256;             // 0..511
        int r = idx >> 2, c = (idx & 3) * 8;
        size_t so = (size_t)(rowBase + r) * DIMM + kb * 32 + c;
        cpa16(smem_u32(&s->Ahi[buf][r][c]), gAhi + so);
        cpa16(smem_u32(&s->Alo[buf][r][c]), gAlo + so);
    }
    #pragma unroll
    for (int it = 0; it < 2; it++) {
        int idx = tid + it * 256;
        int r = idx >> 4, c = (idx & 15) * 8;
        size_t so = (size_t)(kb * 32 + r) * Nn + colBase + c;
        cpa16(smem_u32(&s->Bhi[buf][r][c]), gBhi + so);
        cpa16(smem_u32(&s->Blo[buf][r][c]), gBlo + so);
    }
}

__device__ __forceinline__ void gemm_compute(
    GemmSmem* s, int buf, int lane, int wm, int wn,
    float acc0[8][4], float acc1[8][4])
{
    #pragma unroll
    for (int ks = 0; ks < 2; ks++) {
        u32 ah0[4], ah1[4], al0[4], al1[4];
        u32 ahb = smem_u32(&s->Ahi[buf][wm * 32 + (lane & 15)][ks * 16 + (lane >> 4) * 8]);
        u32 alb = smem_u32(&s->Alo[buf][wm * 32 + (lane & 15)][ks * 16 + (lane >> 4) * 8]);
        ldm_x4(ah0, ahb); ldm_x4(ah1, ahb + 16 * 80);
        ldm_x4(al0, alb); ldm_x4(al1, alb + 16 * 80);
        u32 bhb = smem_u32(&s->Bhi[buf][ks * 16 + (lane & 15)][wn * 64 + (lane >> 4) * 8]);
        u32 blb = smem_u32(&s->Blo[buf][ks * 16 + (lane & 15)][wn * 64 + (lane >> 4) * 8]);
        #pragma unroll
        for (int np = 0; np < 4; np++) {       // two n-tiles per x4t
            u32 bh[4], bl[4];
            ldm_x4t(bh, bhb + np * 32);
            ldm_x4t(bl, blb + np * 32);
            #pragma unroll
            for (int half = 0; half < 2; half++) {
                int nt = np * 2 + half;
                u32 b0h = bh[half * 2], b1h = bh[half * 2 + 1];
                u32 b0l = bl[half * 2], b1l = bl[half * 2 + 1];
                mma16816(acc0[nt][0], acc0[nt][1], acc0[nt][2], acc0[nt][3],
                         ah0[0], ah0[1], ah0[2], ah0[3], b0h, b1h);
                mma16816(acc0[nt][0], acc0[nt][1], acc0[nt][2], acc0[nt][3],
                         ah0[0], ah0[1], ah0[2], ah0[3], b0l, b1l);
                mma16816(acc0[nt][0], acc0[nt][1], acc0[nt][2], acc0[nt][3],
                         al0[0], al0[1], al0[2], al0[3], b0h, b1h);
                mma16816(acc1[nt][0], acc1[nt][1], acc1[nt][2], acc1[nt][3],
                         ah1[0], ah1[1], ah1[2], ah1[3], b0h, b1h);
                mma16816(acc1[nt][0], acc1[nt][1], acc1[nt][2], acc1[nt][3],
                         ah1[0], ah1[1], ah1[2], ah1[3], b0l, b1l);
                mma16816(acc1[nt][0], acc1[nt][1], acc1[nt][2], acc1[nt][3],
                         al1[0], al1[1], al1[2], al1[3], b0h, b1h);
            }
        }
    }
}

__device__ __forceinline__ void gemm_run(
    GemmSmem* s, const h16* gAhi, const h16* gAlo,
    const h16* gBhi, const h16* gBlo,
    int Nn, int rowBase, int colBase, int tid, int lane, int wm, int wn,
    float acc0[8][4], float acc1[8][4])
{
    gemm_issue(s, 0, gAhi, gAlo, gBhi, gBlo, Nn, rowBase, colBase, 0, tid);
    CP_COMMIT();
    for (int kb = 0; kb < 4; kb++) {
        if (kb < 3) {
            gemm_issue(s, (kb + 1) & 1, gAhi, gAlo, gBhi, gBlo,
                       Nn, rowBase, colBase, kb + 1, tid);
            CP_COMMIT();
            CP_WAIT(1);
        } else {
            CP_WAIT(0);
        }
        __syncthreads();
        gemm_compute(s, kb & 1, lane, wm, wn, acc0, acc1);
        __syncthreads();
    }
}

// GEMM1: qkv = x @ Wqkv; q,k -> single fp16; v -> split hi/lo
__global__ __launch_bounds__(256)
void gemm1_kernel()
{
    extern __shared__ char smraw[];
    GemmSmem* s = (GemmSmem*)smraw;
    const int tid = threadIdx.x, lane = tid & 31, w = tid >> 5;
    const int wm = w >> 1, wn = w & 1;
    const int rowBase = blockIdx.y * 128;
    const int cb = blockIdx.x;             // 0=q, 1=k, 2=v

    float acc0[8][4] = {}, acc1[8][4] = {};
    gemm_run(s, g_xhi, g_xlo, g_wqhi, g_wqlo, 384, rowBase, cb * 128,
             tid, lane, wm, wn, acc0, acc1);

    const int gid = lane >> 2, q4 = lane & 3;
    if (cb < 2) {
        h16* dq = cb ? g_k : g_q;
        #pragma unroll
        for (int half = 0; half < 2; half++) {
            const int r0 = rowBase + wm * 32 + half * 16 + gid;
            #pragma unroll
            for (int nt = 0; nt < 8; nt++) {
                float* a = half ? acc1[nt] : acc0[nt];
                int cc = wn * 64 + nt * 8 + q4 * 2;
                *(u32*)&dq[(size_t)r0 * DIMM + cc]       = cvt2h(a[1], a[0]);
                *(u32*)&dq[(size_t)(r0 + 8) * DIMM + cc] = cvt2h(a[3], a[2]);
            }
        }
    } else {
        #pragma unroll
        for (int half = 0; half < 2; half++) {
            const int r0 = rowBase + wm * 32 + half * 16 + gid;
            #pragma unroll
            for (int nt = 0; nt < 8; nt++) {
                float* a = half ? acc1[nt] : acc0[nt];
                int cc = wn * 64 + nt * 8 + q4 * 2;
                u32 hp, lp;
                split2h(a[0], a[1], hp, lp);
                *(u32*)&g_vhi[(size_t)r0 * DIMM + cc] = hp;
                *(u32*)&g_vlo[(size_t)r0 * DIMM + cc] = lp;
                split2h(a[2], a[3], hp, lp);
                *(u32*)&g_vhi[(size_t)(r0 + 8) * DIMM + cc] = hp;
                *(u32*)&g_vlo[(size_t)(r0 + 8) * DIMM + cc] = lp;
            }
        }
    }
}

// GEMM2: out = ao @ Wout + bout (fp32 epilogue)
__global__ __launch_bounds__(256)
void gemm2_kernel(const float* __restrict__ bias, float* __restrict__ out)
{
    extern __shared__ char smraw[];
    GemmSmem* s = (GemmSmem*)smraw;
    const int tid = threadIdx.x, lane = tid & 31, w = tid >> 5;
    const int wm = w >> 1, wn = w & 1;
    const int rowBase = blockIdx.y * 128;

    float acc0[8][4] = {}, acc1[8][4] = {};
    gemm_run(s, g_aohi, g_aolo, g_wohi, g_wolo, 128, rowBase, 0,
             tid, lane, wm, wn, acc0, acc1);

    const int gid = lane >> 2, q4 = lane & 3;
    #pragma unroll
    for (int half = 0; half < 2; half++) {
        const int r0 = rowBase + wm * 32 + half * 16 + gid;
        #pragma unroll
        for (int nt = 0; nt < 8; nt++) {
            float* a = half ? acc1[nt] : acc0[nt];
            int cc = wn * 64 + nt * 8 + q4 * 2;
            float2 bv = *(const float2*)&bias[cc];
            *(float2*)&out[(size_t)r0 * DIMM + cc] =
                make_float2(a[0] + bv.x, a[1] + bv.y);
            *(float2*)&out[(size_t)(r0 + 8) * DIMM + cc] =
                make_float2(a[2] + bv.x, a[3] + bv.y);
        }
    }
}

// ===========================================================================
// Warp-MMA flash attention: single-fp16 S and P, fp16x2 V.
// cp.async double-buffered K/V. klog C-init masking. Split PV accumulators.
// ===========================================================================
struct AttnSmem {
    __align__(16) h16 QT[128][24];        // 48B stride
    __align__(16) h16 KT[2][128][24];
    __align__(16) h16 VHI[2][128][24];
    __align__(16) h16 VLO[2][128][24];
    float klog[NN];
};

__device__ __forceinline__ void attn_issue(AttnSmem* s, int buf, int j0,
                                           int b, int h, int tid)
{
    int r = tid >> 1, c8 = (tid & 1) * 8;      // 128 rows x 2 vec8
    size_t src = (size_t)(b * NN + j0 + r) * DIMM + h * DD + c8;
    cpa16(smem_u32(&s->KT [buf][r][c8]), g_k   + src);
    cpa16(smem_u32(&s->VHI[buf][r][c8]), g_vhi + src);
    cpa16(smem_u32(&s->VLO[buf][r][c8]), g_vlo + src);
}

__global__ __launch_bounds__(256, 2)
void attn_mma_kernel(const float* __restrict__ mask,   // [N-1]
                     const float* __restrict__ maps)   // [B, N-1]
{
    extern __shared__ char smraw[];
    AttnSmem* s = (AttnSmem*)smraw;

    const int tid  = threadIdx.x;
    const int lane = tid & 31;
    const int w    = tid >> 5;
    const int bx   = blockIdx.x;
    const int b    = bx >> 6;
    const int h    = (bx >> 3) & 7;
    const int mt   = bx & 7;
    const int qrow0 = b * NN + mt * 128;
    const float NEGINF = __int_as_float(0xff800000);

    // Q staging + KV block 0 in group 0
    {
        int r = tid >> 1, c8 = (tid & 1) * 8;
        cpa16(smem_u32(&s->QT[r][c8]),
              g_q + (size_t)(qrow0 + r) * DIMM + h * DD + c8);
    }
    attn_issue(s, 0, 0, b, h, tid);
    CP_COMMIT();

    // klog[j] = 0 if kept else -inf
    for (int j = tid; j < NN; j += 256) {
        bool kp = (j == 0) ||
                  (mask[j - 1] != 0.0f && maps[b * (NN - 1) + j - 1] != 0.0f);
        s->klog[j] = kp ? 0.0f : NEGINF;
    }

    const u32 kb0  = smem_u32(&s->KT [0][lane & 7 ][((lane >> 3) & 1) * 8]);
    const u32 vhb0 = smem_u32(&s->VHI[0][lane & 15][(lane >> 4) * 8]);
    const u32 vlb0 = smem_u32(&s->VLO[0][lane & 15][(lane >> 4) * 8]);

    u32 qh[4];
    float oA[2][4] = {}, oB[2][4] = {};
    float lsum0 = 0.0f, lsum1 = 0.0f;

    for (int kb = 0; kb < 8; kb++) {
        if (kb < 7) {
            attn_issue(s, (kb + 1) & 1, (kb + 1) * 128, b, h, tid);
            CP_COMMIT();
            CP_WAIT(1);
        } else {
            CP_WAIT(0);
        }
        __syncthreads();

        if (kb == 0) {
            ldm_x4(qh, smem_u32(&s->QT[w * 16 + (lane & 15)][(lane >> 4) * 8]));
        }

        const int buf = kb & 1;
        const u32 kbase  = kb0  + buf * 6144;
        const u32 vhbase = vhb0 + buf * 6144;
        const u32 vlbase = vlb0 + buf * 6144;
        const int j0 = kb * 128;

        // ---- S = Q.K^T (single MMA) with klog C-init; P -> fp16 ----
        u32 phi[32];
        #pragma unroll
        for (int nt = 0; nt < 16; nt++) {
            u32 kf[2];
            ldm_x2(kf, kbase + nt * 8 * 48);
            float2 kl = *(const float2*)&s->klog[j0 + nt * 8 + (lane & 3) * 2];
            float c0 = kl.x, c1 = kl.y, c2 = kl.x, c3 = kl.y;
            mma16816(c0, c1, c2, c3, qh[0], qh[1], qh[2], qh[3], kf[0], kf[1]);

            float p0 = ex2f(c0), p1 = ex2f(c1), p2 = ex2f(c2), p3 = ex2f(c3);
            lsum0 += p0 + p1;
            lsum1 += p2 + p3;
            phi[nt * 2]     = cvt2h(p1, p0);
            phi[nt * 2 + 1] = cvt2h(p3, p2);
        }

        // ---- O += P.Vhi (oA) + P.Vlo (oB), both n-tiles per x4t ----
        #pragma unroll
        for (int t = 0; t < 8; t++) {
            const u32 vrow = t * 16 * 48;
            u32 vh[4], vl[4];
            ldm_x4t(vh, vhbase + vrow);
            ldm_x4t(vl, vlbase + vrow);
            #pragma unroll
            for (int nt = 0; nt < 2; nt++) {
                mma16816(oA[nt][0], oA[nt][1], oA[nt][2], oA[nt][3],
                         phi[4 * t], phi[4 * t + 1], phi[4 * t + 2], phi[4 * t + 3],
                         vh[nt * 2], vh[nt * 2 + 1]);
                mma16816(oB[nt][0], oB[nt][1], oB[nt][2], oB[nt][3],
                         phi[4 * t], phi[4 * t + 1], phi[4 * t + 2], phi[4 * t + 3],
                         vl[nt * 2], vl[nt * 2 + 1]);
            }
        }
        __syncthreads();
    }

    // ---- reduce l within quads, normalize, write split ao ----
    lsum0 += __shfl_xor_sync(0xffffffffu, lsum0, 1);
    lsum0 += __shfl_xor_sync(0xffffffffu, lsum0, 2);
    lsum1 += __shfl_xor_sync(0xffffffffu, lsum1, 1);
    lsum1 += __shfl_xor_sync(0xffffffffu, lsum1, 2);
    const float inv0 = 1.0f / lsum0;
    const float inv1 = 1.0f / lsum1;

    const int gid  = lane >> 2;
    const int tid4 = lane & 3;
    size_t row0 = (size_t)(qrow0 + w * 16 + gid) * DIMM + h * DD;
    size_t row1 = row0 + 8 * DIMM;
    #pragma unroll
    for (int nt = 0; nt < 2; nt++) {
        int cc = nt * 8 + tid4 * 2;
        u32 hp, lp;
        split2h((oA[nt][0] + oB[nt][0]) * inv0,
                (oA[nt][1] + oB[nt][1]) * inv0, hp, lp);
        *(u32*)&g_aohi[row0 + cc] = hp;
        *(u32*)&g_aolo[row0 + cc] = lp;
        split2h((oA[nt][2] + oB[nt][2]) * inv1,
                (oA[nt][3] + oB[nt][3]) * inv1, hp, lp);
        *(u32*)&g_aohi[row1 + cc] = hp;
        *(u32*)&g_aolo[row1 + cc] = lp;
    }
}

// ---------------------------------------------------------------------------

extern "C" void kernel_launch(void* const* d_in, const int* in_sizes, int n_in,
                              void* d_out, int out_size)
{
    const float* x    = (const float*)d_in[0];
    const float* mask = (const float*)d_in[1];
    const float* maps = (const float*)d_in[2];
    const float* Wqkv = (const float*)d_in[3];
    const float* Wout = (const float*)d_in[4];
    const float* bout = (const float*)d_in[5];
    float* out = (float*)d_out;

    static bool attr_set = false;
    if (!attr_set) {
        cudaFuncSetAttribute(gemm1_kernel,
            cudaFuncAttributeMaxDynamicSharedMemorySize, (int)sizeof(GemmSmem));
        cudaFuncSetAttribute(gemm2_kernel,
            cudaFuncAttributeMaxDynamicSharedMemorySize, (int)sizeof(GemmSmem));
        cudaFuncSetAttribute(attn_mma_kernel,
            cudaFuncAttributeMaxDynamicSharedMemorySize, (int)sizeof(AttnSmem));
        attr_set = true;
    }

    // 0) split inputs into hi/lo f16 (QSC folded into q-cols of Wqkv)
    prep_kernel<<<1024, 256>>>(x, Wqkv, Wout);

    // 1) qkv = x @ Wqkv  (q,k single fp16; v split)
    gemm1_kernel<<<dim3(3, 128), 256, sizeof(GemmSmem)>>>();

    // 2) warp-MMA flash attention (split ao epilogue)
    attn_mma_kernel<<<BB * HH * 8, 256, sizeof(AttnSmem)>>>(mask, maps);

    // 3) out = ao @ Wout + bout
    gemm2_kernel<<<dim3(1, 128), 256, sizeof(GemmSmem)>>>(bout, out);
}

// round 13
// speedup vs baseline: 1.9182x; 1.2653x over previous
#include <cuda_runtime.h>
#include <cuda_fp16.h>
#include <cstdint>

#define BB   16
#define NN   1024
#define DIMM 128
#define HH   8
#define DD   16
#define QSC  (0.08838834764831845f * 1.4426950408889634f)
#define XE   (BB * NN * DIMM)   // 2097152

typedef unsigned long long u64;
typedef unsigned int u32;
typedef __half h16;

// ---------------- pre-split scratch (no cudaMalloc allowed) ----------------
__device__ __align__(16) h16 g_xhi[XE],  g_xlo[XE];
__device__ __align__(16) h16 g_wqhi[DIMM * 384], g_wqlo[DIMM * 384];
__device__ __align__(16) h16 g_wohi[DIMM * DIMM], g_wolo[DIMM * DIMM];
__device__ __align__(16) h16 g_q[XE];    // single fp16, QSC*log2e folded
__device__ __align__(16) h16 g_k[XE];    // single fp16
__device__ __align__(16) h16 g_v[XE];    // single fp16
__device__ __align__(16) h16 g_ao[XE];   // single fp16

// ---------------------------- helpers --------------------------------------
__device__ __forceinline__ u32 smem_u32(const void* p) {
    u32 a;
    asm("{ .reg .u64 t; cvta.to.shared.u64 t, %1; cvt.u32.u64 %0, t; }"
        : "=r"(a) : "l"(p));
    return a;
}
__device__ __forceinline__ void mma16816(float& d0, float& d1, float& d2, float& d3,
                                         u32 a0, u32 a1, u32 a2, u32 a3,
                                         u32 b0, u32 b1) {
    asm volatile(
        "mma.sync.aligned.m16n8k16.row.col.f32.f16.f16.f32 "
        "{%0,%1,%2,%3}, {%4,%5,%6,%7}, {%8,%9}, {%0,%1,%2,%3};"
        : "+f"(d0), "+f"(d1), "+f"(d2), "+f"(d3)
        : "r"(a0), "r"(a1), "r"(a2), "r"(a3), "r"(b0), "r"(b1));
}
__device__ __forceinline__ void ldm_x4(u32* r, u32 addr) {
    asm volatile("ldmatrix.sync.aligned.m8n8.x4.shared.b16 {%0,%1,%2,%3}, [%4];"
                 : "=r"(r[0]), "=r"(r[1]), "=r"(r[2]), "=r"(r[3])
                 : "r"(addr) : "memory");
}
__device__ __forceinline__ void ldm_x2(u32* r, u32 addr) {
    asm volatile("ldmatrix.sync.aligned.m8n8.x2.shared.b16 {%0,%1}, [%2];"
                 : "=r"(r[0]), "=r"(r[1])
                 : "r"(addr) : "memory");
}
__device__ __forceinline__ void ldm_x4t(u32* r, u32 addr) {
    asm volatile("ldmatrix.sync.aligned.m8n8.x4.trans.shared.b16 {%0,%1,%2,%3}, [%4];"
                 : "=r"(r[0]), "=r"(r[1]), "=r"(r[2]), "=r"(r[3])
                 : "r"(addr) : "memory");
}
__device__ __forceinline__ float ex2f(float x) {
    float r; asm("ex2.approx.f32 %0, %1;" : "=f"(r) : "f"(x));
    return r;
}
__device__ __forceinline__ u32 cvt2h(float e1, float e0) {  // f16x2, e0 low
    u32 r; asm("cvt.rn.satfinite.f16x2.f32 %0, %1, %2;" : "=r"(r) : "f"(e1), "f"(e0));
    return r;
}
__device__ __forceinline__ void split2h(float a0, float a1, u32& hp, u32& lp) {
    hp = cvt2h(a1, a0);
    __half2 h = *(__half2*)&hp;
    lp = cvt2h(a1 - __high2float(h), a0 - __low2float(h));
}
__device__ __forceinline__ void cpa16(u32 dst, const void* src) {
    asm volatile("cp.async.cg.shared.global [%0], [%1], 16;"
                 :: "r"(dst), "l"(src) : "memory");
}
#define CP_COMMIT() asm volatile("cp.async.commit_group;" ::: "memory")
#define CP_WAIT(n)  asm volatile("cp.async.wait_group %0;" :: "n"(n) : "memory")

// ===========================================================================
// Prep: split fp32 inputs into hi/lo f16 (QSC folded into q-columns of Wqkv)
// ===========================================================================
__global__ __launch_bounds__(256)
void prep_kernel(const float* __restrict__ x, const float* __restrict__ Wqkv,
                 const float* __restrict__ Wout)
{
    const int stride = gridDim.x * blockDim.x;
    const int t0 = blockIdx.x * blockDim.x + threadIdx.x;

    for (int i = t0; i < XE / 2; i += stride) {
        float2 v = ((const float2*)x)[i];
        u32 hp, lp; split2h(v.x, v.y, hp, lp);
        ((u32*)g_xhi)[i] = hp; ((u32*)g_xlo)[i] = lp;
    }
    for (int i = t0; i < DIMM * 384 / 2; i += stride) {
        float2 v = ((const float2*)Wqkv)[i];
        if (((2 * i) % 384) < 128) { v.x *= QSC; v.y *= QSC; }
        u32 hp, lp; split2h(v.x, v.y, hp, lp);
        ((u32*)g_wqhi)[i] = hp; ((u32*)g_wqlo)[i] = lp;
    }
    for (int i = t0; i < DIMM * DIMM / 2; i += stride) {
        float2 v = ((const float2*)Wout)[i];
        u32 hp, lp; split2h(v.x, v.y, hp, lp);
        ((u32*)g_wohi)[i] = hp; ((u32*)g_wolo)[i] = lp;
    }
}

// ===========================================================================
// warp-MMA GEMM, cp.async double-buffered (R10 shape).
// CTA tile 128x128, 8 warps as 4(m)x2(n), warp tile m32xn64, K chunks of 32.
// ASP=true: A split hi/lo (3-term fp16x3). ASP=false: A single (2-term).
// ===========================================================================
struct GemmSmem {
    __align__(16) h16 Ahi[2][128][40];   // 80B row stride
    __align__(16) h16 Alo[2][128][40];   // unused when !ASP
    __align__(16) h16 Bhi[2][32][136];   // 272B row stride
    __align__(16) h16 Blo[2][32][136];
};

template<bool ASP>
__device__ __forceinline__ void gemm_issue(
    GemmSmem* s, int buf,
    const h16* gAhi, const h16* gAlo, const h16* gBhi, const h16* gBlo,
    int Nn, int rowBase, int colBase, int kb, int tid)
{
    #pragma unroll
    for (int it = 0; it < 2; it++) {
        int idx = tid + it * 256;             // 0..511
        int r = idx >> 2, c = (idx & 3) * 8;
        size_t so = (size_t)(rowBase + r) * DIMM + kb * 32 + c;
        cpa16(smem_u32(&s->Ahi[buf][r][c]), gAhi + so);
        if (ASP) cpa16(smem_u32(&s->Alo[buf][r][c]), gAlo + so);
    }
    #pragma unroll
    for (int it = 0; it < 2; it++) {
        int idx = tid + it * 256;
        int r = idx >> 4, c = (idx & 15) * 8;
        size_t so = (size_t)(kb * 32 + r) * Nn + colBase + c;
        cpa16(smem_u32(&s->Bhi[buf][r][c]), gBhi + so);
        cpa16(smem_u32(&s->Blo[buf][r][c]), gBlo + so);
    }
}

template<bool ASP>
__device__ __forceinline__ void gemm_compute(
    GemmSmem* s, int buf, int lane, int wm, int wn,
    float acc0[8][4], float acc1[8][4])
{
    #pragma unroll
    for (int ks = 0; ks < 2; ks++) {
        u32 ah0[4], ah1[4], al0[4], al1[4];
        u32 ahb = smem_u32(&s->Ahi[buf][wm * 32 + (lane & 15)][ks * 16 + (lane >> 4) * 8]);
        ldm_x4(ah0, ahb); ldm_x4(ah1, ahb + 16 * 80);
        if (ASP) {
            u32 alb = smem_u32(&s->Alo[buf][wm * 32 + (lane & 15)][ks * 16 + (lane >> 4) * 8]);
            ldm_x4(al0, alb); ldm_x4(al1, alb + 16 * 80);
        }
        u32 bhb = smem_u32(&s->Bhi[buf][ks * 16 + (lane & 15)][wn * 64 + (lane >> 4) * 8]);
        u32 blb = smem_u32(&s->Blo[buf][ks * 16 + (lane & 15)][wn * 64 + (lane >> 4) * 8]);
        #pragma unroll
        for (int np = 0; np < 4; np++) {       // two n-tiles per x4t
            u32 bh[4], bl[4];
            ldm_x4t(bh, bhb + np * 32);
            ldm_x4t(bl, blb + np * 32);
            #pragma unroll
            for (int half = 0; half < 2; half++) {
                int nt = np * 2 + half;
                u32 b0h = bh[half * 2], b1h = bh[half * 2 + 1];
                u32 b0l = bl[half * 2], b1l = bl[half * 2 + 1];
                mma16816(acc0[nt][0], acc0[nt][1], acc0[nt][2], acc0[nt][3],
                         ah0[0], ah0[1], ah0[2], ah0[3], b0h, b1h);
                mma16816(acc0[nt][0], acc0[nt][1], acc0[nt][2], acc0[nt][3],
                         ah0[0], ah0[1], ah0[2], ah0[3], b0l, b1l);
                if (ASP)
                    mma16816(acc0[nt][0], acc0[nt][1], acc0[nt][2], acc0[nt][3],
                             al0[0], al0[1], al0[2], al0[3], b0h, b1h);
                mma16816(acc1[nt][0], acc1[nt][1], acc1[nt][2], acc1[nt][3],
                         ah1[0], ah1[1], ah1[2], ah1[3], b0h, b1h);
                mma16816(acc1[nt][0], acc1[nt][1], acc1[nt][2], acc1[nt][3],
                         ah1[0], ah1[1], ah1[2], ah1[3], b0l, b1l);
                if (ASP)
                    mma16816(acc1[nt][0], acc1[nt][1], acc1[nt][2], acc1[nt][3],
                             al1[0], al1[1], al1[2], al1[3], b0h, b1h);
            }
        }
    }
}

template<bool ASP>
__device__ __forceinline__ void gemm_run(
    GemmSmem* s, const h16* gAhi, const h16* gAlo,
    const h16* gBhi, const h16* gBlo,
    int Nn, int rowBase, int colBase, int tid, int lane, int wm, int wn,
    float acc0[8][4], float acc1[8][4])
{
    gemm_issue<ASP>(s, 0, gAhi, gAlo, gBhi, gBlo, Nn, rowBase, colBase, 0, tid);
    CP_COMMIT();
    for (int kb = 0; kb < 4; kb++) {
        if (kb < 3) {
            gemm_issue<ASP>(s, (kb + 1) & 1, gAhi, gAlo, gBhi, gBlo,
                            Nn, rowBase, colBase, kb + 1, tid);
            CP_COMMIT();
            CP_WAIT(1);
        } else {
            CP_WAIT(0);
        }
        __syncthreads();
        gemm_compute<ASP>(s, kb & 1, lane, wm, wn, acc0, acc1);
        __syncthreads();
    }
}

// GEMM1: qkv = x @ Wqkv; q,k,v -> single fp16
__global__ __launch_bounds__(256)
void gemm1_kernel()
{
    extern __shared__ char smraw[];
    GemmSmem* s = (GemmSmem*)smraw;
    const int tid = threadIdx.x, lane = tid & 31, w = tid >> 5;
    const int wm = w >> 1, wn = w & 1;
    const int rowBase = blockIdx.y * 128;
    const int cb = blockIdx.x;             // 0=q, 1=k, 2=v

    float acc0[8][4] = {}, acc1[8][4] = {};
    gemm_run<true>(s, g_xhi, g_xlo, g_wqhi, g_wqlo, 384, rowBase, cb * 128,
                   tid, lane, wm, wn, acc0, acc1);

    h16* dst = (cb == 0) ? g_q : (cb == 1) ? g_k : g_v;
    const int gid = lane >> 2, q4 = lane & 3;
    #pragma unroll
    for (int half = 0; half < 2; half++) {
        const int r0 = rowBase + wm * 32 + half * 16 + gid;
        #pragma unroll
        for (int nt = 0; nt < 8; nt++) {
            float* a = half ? acc1[nt] : acc0[nt];
            int cc = wn * 64 + nt * 8 + q4 * 2;
            *(u32*)&dst[(size_t)r0 * DIMM + cc]       = cvt2h(a[1], a[0]);
            *(u32*)&dst[(size_t)(r0 + 8) * DIMM + cc] = cvt2h(a[3], a[2]);
        }
    }
}

// GEMM2: out = ao @ Wout + bout (A single fp16, fp32 epilogue)
__global__ __launch_bounds__(256)
void gemm2_kernel(const float* __restrict__ bias, float* __restrict__ out)
{
    extern __shared__ char smraw[];
    GemmSmem* s = (GemmSmem*)smraw;
    const int tid = threadIdx.x, lane = tid & 31, w = tid >> 5;
    const int wm = w >> 1, wn = w & 1;
    const int rowBase = blockIdx.y * 128;

    float acc0[8][4] = {}, acc1[8][4] = {};
    gemm_run<false>(s, g_ao, nullptr, g_wohi, g_wolo, 128, rowBase, 0,
                    tid, lane, wm, wn, acc0, acc1);

    const int gid = lane >> 2, q4 = lane & 3;
    #pragma unroll
    for (int half = 0; half < 2; half++) {
        const int r0 = rowBase + wm * 32 + half * 16 + gid;
        #pragma unroll
        for (int nt = 0; nt < 8; nt++) {
            float* a = half ? acc1[nt] : acc0[nt];
            int cc = wn * 64 + nt * 8 + q4 * 2;
            float2 bv = *(const float2*)&bias[cc];
            *(float2*)&out[(size_t)r0 * DIMM + cc] =
                make_float2(a[0] + bv.x, a[1] + bv.y);
            *(float2*)&out[(size_t)(r0 + 8) * DIMM + cc] =
                make_float2(a[2] + bv.x, a[3] + bv.y);
        }
    }
}

// ===========================================================================
// Warp-MMA flash attention: single-fp16 S, P, V.
// cp.async double-buffered K/V. klog C-init masking.
// ===========================================================================
struct AttnSmem {
    __align__(16) h16 QT[128][24];        // 48B stride
    __align__(16) h16 KT[2][128][24];
    __align__(16) h16 VT[2][128][24];
    float klog[NN];
};

__device__ __forceinline__ void attn_issue(AttnSmem* s, int buf, int j0,
                                           int b, int h, int tid)
{
    int r = tid >> 1, c8 = (tid & 1) * 8;      // 128 rows x 2 vec8
    size_t src = (size_t)(b * NN + j0 + r) * DIMM + h * DD + c8;
    cpa16(smem_u32(&s->KT[buf][r][c8]), g_k + src);
    cpa16(smem_u32(&s->VT[buf][r][c8]), g_v + src);
}

__global__ __launch_bounds__(256, 3)
void attn_mma_kernel(const float* __restrict__ mask,   // [N-1]
                     const float* __restrict__ maps)   // [B, N-1]
{
    extern __shared__ char smraw[];
    AttnSmem* s = (AttnSmem*)smraw;

    const int tid  = threadIdx.x;
    const int lane = tid & 31;
    const int w    = tid >> 5;
    const int bx   = blockIdx.x;
    const int b    = bx >> 6;
    const int h    = (bx >> 3) & 7;
    const int mt   = bx & 7;
    const int qrow0 = b * NN + mt * 128;
    const float NEGINF = __int_as_float(0xff800000);

    // Q staging + KV block 0 in group 0
    {
        int r = tid >> 1, c8 = (tid & 1) * 8;
        cpa16(smem_u32(&s->QT[r][c8]),
              g_q + (size_t)(qrow0 + r) * DIMM + h * DD + c8);
    }
    attn_issue(s, 0, 0, b, h, tid);
    CP_COMMIT();

    // klog[j] = 0 if kept else -inf
    for (int j = tid; j < NN; j += 256) {
        bool kp = (j == 0) ||
                  (mask[j - 1] != 0.0f && maps[b * (NN - 1) + j - 1] != 0.0f);
        s->klog[j] = kp ? 0.0f : NEGINF;
    }

    const u32 kb0 = smem_u32(&s->KT[0][lane & 7 ][((lane >> 3) & 1) * 8]);
    const u32 vb0 = smem_u32(&s->VT[0][lane & 15][(lane >> 4) * 8]);

    u32 qh[4];
    float oA[2][4] = {};
    float lsum0 = 0.0f, lsum1 = 0.0f;

    for (int kb = 0; kb < 8; kb++) {
        if (kb < 7) {
            attn_issue(s, (kb + 1) & 1, (kb + 1) * 128, b, h, tid);
            CP_COMMIT();
            CP_WAIT(1);
        } else {
            CP_WAIT(0);
        }
        __syncthreads();

        if (kb == 0) {
            ldm_x4(qh, smem_u32(&s->QT[w * 16 + (lane & 15)][(lane >> 4) * 8]));
        }

        const int buf = kb & 1;
        const u32 kbase = kb0 + buf * 6144;
        const u32 vbase = vb0 + buf * 6144;
        const int j0 = kb * 128;

        // ---- S = Q.K^T (single MMA) with klog C-init; P -> fp16 ----
        u32 phi[32];
        #pragma unroll
        for (int nt = 0; nt < 16; nt++) {
            u32 kf[2];
            ldm_x2(kf, kbase + nt * 8 * 48);
            float2 kl = *(const float2*)&s->klog[j0 + nt * 8 + (lane & 3) * 2];
            float c0 = kl.x, c1 = kl.y, c2 = kl.x, c3 = kl.y;
            mma16816(c0, c1, c2, c3, qh[0], qh[1], qh[2], qh[3], kf[0], kf[1]);

            float p0 = ex2f(c0), p1 = ex2f(c1), p2 = ex2f(c2), p3 = ex2f(c3);
            lsum0 += p0 + p1;
            lsum1 += p2 + p3;
            phi[nt * 2]     = cvt2h(p1, p0);
            phi[nt * 2 + 1] = cvt2h(p3, p2);
        }

        // ---- O += P.V  (8 k16-steps, 2 n-tiles per x4t) ----
        #pragma unroll
        for (int t = 0; t < 8; t++) {
            u32 vh[4];
            ldm_x4t(vh, vbase + t * 16 * 48);
            #pragma unroll
            for (int nt = 0; nt < 2; nt++) {
                mma16816(oA[nt][0], oA[nt][1], oA[nt][2], oA[nt][3],
                         phi[4 * t], phi[4 * t + 1], phi[4 * t + 2], phi[4 * t + 3],
                         vh[nt * 2], vh[nt * 2 + 1]);
            }
        }
        __syncthreads();
    }

    // ---- reduce l within quads, normalize, write single-fp16 ao ----
    lsum0 += __shfl_xor_sync(0xffffffffu, lsum0, 1);
    lsum0 += __shfl_xor_sync(0xffffffffu, lsum0, 2);
    lsum1 += __shfl_xor_sync(0xffffffffu, lsum1, 1);
    lsum1 += __shfl_xor_sync(0xffffffffu, lsum1, 2);
    const float inv0 = 1.0f / lsum0;
    const float inv1 = 1.0f / lsum1;

    const int gid  = lane >> 2;
    const int tid4 = lane & 3;
    size_t row0 = (size_t)(qrow0 + w * 16 + gid) * DIMM + h * DD;
    size_t row1 = row0 + 8 * DIMM;
    #pragma unroll
    for (int nt = 0; nt < 2; nt++) {
        int cc = nt * 8 + tid4 * 2;
        *(u32*)&g_ao[row0 + cc] = cvt2h(oA[nt][1] * inv0, oA[nt][0] * inv0);
        *(u32*)&g_ao[row1 + cc] = cvt2h(oA[nt][3] * inv1, oA[nt][2] * inv1);
    }
}

// ---------------------------------------------------------------------------

extern "C" void kernel_launch(void* const* d_in, const int* in_sizes, int n_in,
                              void* d_out, int out_size)
{
    const float* x    = (const float*)d_in[0];
    const float* mask = (const float*)d_in[1];
    const float* maps = (const float*)d_in[2];
    const float* Wqkv = (const float*)d_in[3];
    const float* Wout = (const float*)d_in[4];
    const float* bout = (const float*)d_in[5];
    float* out = (float*)d_out;

    static bool attr_set = false;
    if (!attr_set) {
        cudaFuncSetAttribute(gemm1_kernel,
            cudaFuncAttributeMaxDynamicSharedMemorySize, (int)sizeof(GemmSmem));
        cudaFuncSetAttribute(gemm2_kernel,
            cudaFuncAttributeMaxDynamicSharedMemorySize, (int)sizeof(GemmSmem));
        cudaFuncSetAttribute(attn_mma_kernel,
            cudaFuncAttributeMaxDynamicSharedMemorySize, (int)sizeof(AttnSmem));
        attr_set = true;
    }

    // 0) split inputs into hi/lo f16 (QSC folded into q-cols of Wqkv)
    prep_kernel<<<1024, 256>>>(x, Wqkv, Wout);

    // 1) qkv = x @ Wqkv  (q,k,v single fp16)
    gemm1_kernel<<<dim3(3, 128), 256, sizeof(GemmSmem)>>>();

    // 2) warp-MMA flash attention (single-fp16 ao)
    attn_mma_kernel<<<BB * HH * 8, 256, sizeof(AttnSmem)>>>(mask, maps);

    // 3) out = ao @ Wout + bout
    gemm2_kernel<<<dim3(1, 128), 256, sizeof(GemmSmem)>>>(bout, out);
}

// round 14
// speedup vs baseline: 2.2059x; 1.1500x over previous
#include <cuda_runtime.h>
#include <cuda_fp16.h>
#include <cstdint>

#define BB   16
#define NN   1024
#define DIMM 128
#define HH   8
#define DD   16
#define QSC  (0.08838834764831845f * 1.4426950408889634f)
#define XE   (BB * NN * DIMM)   // 2097152

typedef unsigned long long u64;
typedef unsigned int u32;
typedef __half h16;

// ---------------- pre-split scratch (no cudaMalloc allowed) ----------------
__device__ __align__(16) h16 g_xh[XE];                      // x single fp16
__device__ __align__(16) h16 g_wqhi[DIMM * 384], g_wqlo[DIMM * 384];
__device__ __align__(16) h16 g_wohi[DIMM * DIMM], g_wolo[DIMM * DIMM];
__device__ __align__(16) h16 g_q[XE];    // single fp16, QSC*log2e folded
__device__ __align__(16) h16 g_k[XE];    // single fp16
__device__ __align__(16) h16 g_v[XE];    // single fp16
__device__ __align__(16) h16 g_ao[XE];   // single fp16

// ---------------------------- helpers --------------------------------------
__device__ __forceinline__ u32 smem_u32(const void* p) {
    u32 a;
    asm("{ .reg .u64 t; cvta.to.shared.u64 t, %1; cvt.u32.u64 %0, t; }"
        : "=r"(a) : "l"(p));
    return a;
}
__device__ __forceinline__ void mma16816(float& d0, float& d1, float& d2, float& d3,
                                         u32 a0, u32 a1, u32 a2, u32 a3,
                                         u32 b0, u32 b1) {
    asm volatile(
        "mma.sync.aligned.m16n8k16.row.col.f32.f16.f16.f32 "
        "{%0,%1,%2,%3}, {%4,%5,%6,%7}, {%8,%9}, {%0,%1,%2,%3};"
        : "+f"(d0), "+f"(d1), "+f"(d2), "+f"(d3)
        : "r"(a0), "r"(a1), "r"(a2), "r"(a3), "r"(b0), "r"(b1));
}
__device__ __forceinline__ void ldm_x4(u32* r, u32 addr) {
    asm volatile("ldmatrix.sync.aligned.m8n8.x4.shared.b16 {%0,%1,%2,%3}, [%4];"
                 : "=r"(r[0]), "=r"(r[1]), "=r"(r[2]), "=r"(r[3])
                 : "r"(addr) : "memory");
}
__device__ __forceinline__ void ldm_x2(u32* r, u32 addr) {
    asm volatile("ldmatrix.sync.aligned.m8n8.x2.shared.b16 {%0,%1}, [%2];"
                 : "=r"(r[0]), "=r"(r[1])
                 : "r"(addr) : "memory");
}
__device__ __forceinline__ void ldm_x2t(u32* r, u32 addr) {
    asm volatile("ldmatrix.sync.aligned.m8n8.x2.trans.shared.b16 {%0,%1}, [%2];"
                 : "=r"(r[0]), "=r"(r[1])
                 : "r"(addr) : "memory");
}
__device__ __forceinline__ void ldm_x4t(u32* r, u32 addr) {
    asm volatile("ldmatrix.sync.aligned.m8n8.x4.trans.shared.b16 {%0,%1,%2,%3}, [%4];"
                 : "=r"(r[0]), "=r"(r[1]), "=r"(r[2]), "=r"(r[3])
                 : "r"(addr) : "memory");
}
__device__ __forceinline__ u32 h2ex2(u32 x) {   // packed fp16x2 ex2
    u32 r; asm("ex2.approx.f16x2 %0, %1;" : "=r"(r) : "r"(x));
    return r;
}
__device__ __forceinline__ u32 cvt2h(float e1, float e0) {  // f16x2, e0 low
    u32 r; asm("cvt.rn.satfinite.f16x2.f32 %0, %1, %2;" : "=r"(r) : "f"(e1), "f"(e0));
    return r;
}
__device__ __forceinline__ void split2h(float a0, float a1, u32& hp, u32& lp) {
    hp = cvt2h(a1, a0);
    __half2 h = *(__half2*)&hp;
    lp = cvt2h(a1 - __high2float(h), a0 - __low2float(h));
}
__device__ __forceinline__ void cpa16(u32 dst, const void* src) {
    asm volatile("cp.async.cg.shared.global [%0], [%1], 16;"
                 :: "r"(dst), "l"(src) : "memory");
}
#define CP_COMMIT() asm volatile("cp.async.commit_group;" ::: "memory")
#define CP_WAIT(n)  asm volatile("cp.async.wait_group %0;" :: "n"(n) : "memory")

// ===========================================================================
// Prep: x -> single fp16; Wqkv/Wout -> hi/lo fp16 (QSC folded into q-cols)
// ===========================================================================
__global__ __launch_bounds__(256)
void prep_kernel(const float* __restrict__ x, const float* __restrict__ Wqkv,
                 const float* __restrict__ Wout)
{
    const int stride = gridDim.x * blockDim.x;
    const int t0 = blockIdx.x * blockDim.x + threadIdx.x;

    for (int i = t0; i < XE / 2; i += stride) {
        float2 v = ((const float2*)x)[i];
        ((u32*)g_xh)[i] = cvt2h(v.y, v.x);
    }
    for (int i = t0; i < DIMM * 384 / 2; i += stride) {
        float2 v = ((const float2*)Wqkv)[i];
        if (((2 * i) % 384) < 128) { v.x *= QSC; v.y *= QSC; }
        u32 hp, lp; split2h(v.x, v.y, hp, lp);
        ((u32*)g_wqhi)[i] = hp; ((u32*)g_wqlo)[i] = lp;
    }
    for (int i = t0; i < DIMM * DIMM / 2; i += stride) {
        float2 v = ((const float2*)Wout)[i];
        u32 hp, lp; split2h(v.x, v.y, hp, lp);
        ((u32*)g_wohi)[i] = hp; ((u32*)g_wolo)[i] = lp;
    }
}

// ===========================================================================
// warp-MMA GEMM, full-K resident smem (K=128), one wait + one sync.
// CTA tile 128x128, 8 warps as 4(m)x2(n), warp tile m32xn64.
// 2-term: A(single fp16) x (Bhi + Blo).
// ===========================================================================
struct GemmSmem {
    __align__(16) h16 A  [128][136];   // 272B row stride
    __align__(16) h16 Bhi[128][136];
    __align__(16) h16 Blo[128][136];
};

__device__ __forceinline__ void gemm_core(
    GemmSmem* s, const h16* gA, const h16* gBhi, const h16* gBlo,
    int Nn, int rowBase, int colBase, int tid, int lane, int wm, int wn,
    float acc0[8][4], float acc1[8][4])
{
    // Issue the ENTIRE K=128 panel up-front (24 cp.async per thread)
    #pragma unroll
    for (int it = 0; it < 8; it++) {
        int idx = tid + it * 256;             // 0..2047
        int r = idx >> 4, c = (idx & 15) * 8;
        cpa16(smem_u32(&s->A[r][c]),   gA   + (size_t)(rowBase + r) * DIMM + c);
        cpa16(smem_u32(&s->Bhi[r][c]), gBhi + (size_t)r * Nn + colBase + c);
        cpa16(smem_u32(&s->Blo[r][c]), gBlo + (size_t)r * Nn + colBase + c);
    }
    CP_COMMIT();
    CP_WAIT(0);
    __syncthreads();

    #pragma unroll
    for (int kk = 0; kk < 8; kk++) {          // k16 steps
        u32 ah0[4], ah1[4];
        u32 ahb = smem_u32(&s->A[wm * 32 + (lane & 15)][kk * 16 + (lane >> 4) * 8]);
        ldm_x4(ah0, ahb);
        ldm_x4(ah1, ahb + 16 * 272);
        u32 bhb = smem_u32(&s->Bhi[kk * 16 + (lane & 15)][wn * 64 + (lane >> 4) * 8]);
        u32 blb = smem_u32(&s->Blo[kk * 16 + (lane & 15)][wn * 64 + (lane >> 4) * 8]);
        #pragma unroll
        for (int np = 0; np < 4; np++) {
            u32 bh[4], bl[4];
            ldm_x4t(bh, bhb + np * 32);
            ldm_x4t(bl, blb + np * 32);
            #pragma unroll
            for (int half = 0; half < 2; half++) {
                int nt = np * 2 + half;
                u32 b0h = bh[half * 2], b1h = bh[half * 2 + 1];
                u32 b0l = bl[half * 2], b1l = bl[half * 2 + 1];
                mma16816(acc0[nt][0], acc0[nt][1], acc0[nt][2], acc0[nt][3],
                         ah0[0], ah0[1], ah0[2], ah0[3], b0h, b1h);
                mma16816(acc0[nt][0], acc0[nt][1], acc0[nt][2], acc0[nt][3],
                         ah0[0], ah0[1], ah0[2], ah0[3], b0l, b1l);
                mma16816(acc1[nt][0], acc1[nt][1], acc1[nt][2], acc1[nt][3],
                         ah1[0], ah1[1], ah1[2], ah1[3], b0h, b1h);
                mma16816(acc1[nt][0], acc1[nt][1], acc1[nt][2], acc1[nt][3],
                         ah1[0], ah1[1], ah1[2], ah1[3], b0l, b1l);
            }
        }
    }
}

// GEMM1: qkv = x @ Wqkv; q,k,v -> single fp16
__global__ __launch_bounds__(256)
void gemm1_kernel()
{
    extern __shared__ char smraw[];
    GemmSmem* s = (GemmSmem*)smraw;
    const int tid = threadIdx.x, lane = tid & 31, w = tid >> 5;
    const int wm = w >> 1, wn = w & 1;
    const int rowBase = blockIdx.y * 128;
    const int cb = blockIdx.x;             // 0=q, 1=k, 2=v

    float acc0[8][4] = {}, acc1[8][4] = {};
    gemm_core(s, g_xh, g_wqhi, g_wqlo, 384, rowBase, cb * 128,
              tid, lane, wm, wn, acc0, acc1);

    h16* dst = (cb == 0) ? g_q : (cb == 1) ? g_k : g_v;
    const int gid = lane >> 2, q4 = lane & 3;
    #pragma unroll
    for (int half = 0; half < 2; half++) {
        const int r0 = rowBase + wm * 32 + half * 16 + gid;
        #pragma unroll
        for (int nt = 0; nt < 8; nt++) {
            float* a = half ? acc1[nt] : acc0[nt];
            int cc = wn * 64 + nt * 8 + q4 * 2;
            *(u32*)&dst[(size_t)r0 * DIMM + cc]       = cvt2h(a[1], a[0]);
            *(u32*)&dst[(size_t)(r0 + 8) * DIMM + cc] = cvt2h(a[3], a[2]);
        }
    }
}

// GEMM2: out = ao @ Wout + bout (fp32 epilogue)
__global__ __launch_bounds__(256)
void gemm2_kernel(const float* __restrict__ bias, float* __restrict__ out)
{
    extern __shared__ char smraw[];
    GemmSmem* s = (GemmSmem*)smraw;
    const int tid = threadIdx.x, lane = tid & 31, w = tid >> 5;
    const int wm = w >> 1, wn = w & 1;
    const int rowBase = blockIdx.y * 128;

    float acc0[8][4] = {}, acc1[8][4] = {};
    gemm_core(s, g_ao, g_wohi, g_wolo, 128, rowBase, 0,
              tid, lane, wm, wn, acc0, acc1);

    const int gid = lane >> 2, q4 = lane & 3;
    #pragma unroll
    for (int half = 0; half < 2; half++) {
        const int r0 = rowBase + wm * 32 + half * 16 + gid;
        #pragma unroll
        for (int nt = 0; nt < 8; nt++) {
            float* a = half ? acc1[nt] : acc0[nt];
            int cc = wn * 64 + nt * 8 + q4 * 2;
            float2 bv = *(const float2*)&bias[cc];
            *(float2*)&out[(size_t)r0 * DIMM + cc] =
                make_float2(a[0] + bv.x, a[1] + bv.y);
            *(float2*)&out[(size_t)(r0 + 8) * DIMM + cc] =
                make_float2(a[2] + bv.x, a[3] + bv.y);
        }
    }
}

// ===========================================================================
// Warp-MMA flash attention: single-fp16 S/P/V, f16x2 ex2, l via ones-column.
// cp.async double-buffered K/V. klog C-init masking.
// ===========================================================================
struct AttnSmem {
    __align__(16) h16 QT[128][24];        // 48B stride
    __align__(16) h16 KT[2][128][24];
    __align__(16) h16 VT[2][128][24];     // cols 0-15 V; col 16 = 1.0; 17-23 = 0
    float klog[NN];
};

__device__ __forceinline__ void attn_issue(AttnSmem* s, int buf, int j0,
                                           int b, int h, int tid)
{
    int r = tid >> 1, c8 = (tid & 1) * 8;      // 128 rows x 2 vec8
    size_t src = (size_t)(b * NN + j0 + r) * DIMM + h * DD + c8;
    cpa16(smem_u32(&s->KT[buf][r][c8]), g_k + src);
    cpa16(smem_u32(&s->VT[buf][r][c8]), g_v + src);
}

__global__ __launch_bounds__(256, 3)
void attn_mma_kernel(const float* __restrict__ mask,   // [N-1]
                     const float* __restrict__ maps)   // [B, N-1]
{
    extern __shared__ char smraw[];
    AttnSmem* s = (AttnSmem*)smraw;

    const int tid  = threadIdx.x;
    const int lane = tid & 31;
    const int w    = tid >> 5;
    const int bx   = blockIdx.x;
    const int b    = bx >> 6;
    const int h    = (bx >> 3) & 7;
    const int mt   = bx & 7;
    const int qrow0 = b * NN + mt * 128;
    const float NEGINF = __int_as_float(0xff800000);

    // Q staging + KV block 0 in group 0
    {
        int r = tid >> 1, c8 = (tid & 1) * 8;
        cpa16(smem_u32(&s->QT[r][c8]),
              g_q + (size_t)(qrow0 + r) * DIMM + h * DD + c8);
    }
    attn_issue(s, 0, 0, b, h, tid);
    CP_COMMIT();

    // klog[j] = 0 if kept else -inf
    for (int j = tid; j < NN; j += 256) {
        bool kp = (j == 0) ||
                  (mask[j - 1] != 0.0f && maps[b * (NN - 1) + j - 1] != 0.0f);
        s->klog[j] = kp ? 0.0f : NEGINF;
    }
    // ones-column (col 16) + zero cols 17-23, both buffers (never overwritten)
    for (int i = tid; i < 2 * 128 * 8; i += 256) {
        int bufi = i >> 10, rem = i & 1023;
        int r = rem >> 3, c = rem & 7;
        s->VT[bufi][r][16 + c] = __float2half(c == 0 ? 1.0f : 0.0f);
    }

    const u32 kb0 = smem_u32(&s->KT[0][lane & 7 ][((lane >> 3) & 1) * 8]);
    const u32 vb0 = smem_u32(&s->VT[0][lane & 15][(lane >> 4) * 8]);
    const u32 lb0 = smem_u32(&s->VT[0][lane & 15][16]);

    u32 qh[4];
    float oA[2][4] = {};
    float oL[4] = {};
    for (int kb = 0; kb < 8; kb++) {
        if (kb < 7) {
            attn_issue(s, (kb + 1) & 1, (kb + 1) * 128, b, h, tid);
            CP_COMMIT();
            CP_WAIT(1);
        } else {
            CP_WAIT(0);
        }
        __syncthreads();

        if (kb == 0) {
            ldm_x4(qh, smem_u32(&s->QT[w * 16 + (lane & 15)][(lane >> 4) * 8]));
        }

        const int buf = kb & 1;
        const u32 kbase = kb0 + buf * 6144;
        const u32 vbase = vb0 + buf * 6144;
        const u32 lbase = lb0 + buf * 6144;
        const int j0 = kb * 128;

        // ---- S = Q.K^T (1 MMA) with klog C-init; P = ex2.f16x2(S) ----
        u32 phi[32];
        #pragma unroll
        for (int nt = 0; nt < 16; nt++) {
            u32 kf[2];
            ldm_x2(kf, kbase + nt * 8 * 48);
            float2 kl = *(const float2*)&s->klog[j0 + nt * 8 + (lane & 3) * 2];
            float c0 = kl.x, c1 = kl.y, c2 = kl.x, c3 = kl.y;
            mma16816(c0, c1, c2, c3, qh[0], qh[1], qh[2], qh[3], kf[0], kf[1]);
            phi[nt * 2]     = h2ex2(cvt2h(c1, c0));
            phi[nt * 2 + 1] = h2ex2(cvt2h(c3, c2));
        }

        // ---- O += P.V  (2 n-tiles) ; l += P.ones (3rd n-tile, col 16) ----
        #pragma unroll
        for (int t = 0; t < 8; t++) {
            u32 vh[4], vl2[2];
            ldm_x4t(vh, vbase + t * 16 * 48);
            ldm_x2t(vl2, lbase + t * 16 * 48);
            #pragma unroll
            for (int nt = 0; nt < 2; nt++) {
                mma16816(oA[nt][0], oA[nt][1], oA[nt][2], oA[nt][3],
                         phi[4 * t], phi[4 * t + 1], phi[4 * t + 2], phi[4 * t + 3],
                         vh[nt * 2], vh[nt * 2 + 1]);
            }
            mma16816(oL[0], oL[1], oL[2], oL[3],
                     phi[4 * t], phi[4 * t + 1], phi[4 * t + 2], phi[4 * t + 3],
                     vl2[0], vl2[1]);
        }
        __syncthreads();
    }

    // ---- l = O col 16 (lane gid*4's d0/d2), normalize, write fp16 ao ----
    const int gid  = lane >> 2;
    const int tid4 = lane & 3;
    float lsum0 = __shfl_sync(0xffffffffu, oL[0], gid * 4);
    float lsum1 = __shfl_sync(0xffffffffu, oL[2], gid * 4);
    const float inv0 = 1.0f / lsum0;
    const float inv1 = 1.0f / lsum1;

    size_t row0 = (size_t)(qrow0 + w * 16 + gid) * DIMM + h * DD;
    size_t row1 = row0 + 8 * DIMM;
    #pragma unroll
    for (int nt = 0; nt < 2; nt++) {
        int cc = nt * 8 + tid4 * 2;
        *(u32*)&g_ao[row0 + cc] = cvt2h(oA[nt][1] * inv0, oA[nt][0] * inv0);
        *(u32*)&g_ao[row1 + cc] = cvt2h(oA[nt][3] * inv1, oA[nt][2] * inv1);
    }
}

// ---------------------------------------------------------------------------

extern "C" void kernel_launch(void* const* d_in, const int* in_sizes, int n_in,
                              void* d_out, int out_size)
{
    const float* x    = (const float*)d_in[0];
    const float* mask = (const float*)d_in[1];
    const float* maps = (const float*)d_in[2];
    const float* Wqkv = (const float*)d_in[3];
    const float* Wout = (const float*)d_in[4];
    const float* bout = (const float*)d_in[5];
    float* out = (float*)d_out;

    static bool attr_set = false;
    if (!attr_set) {
        cudaFuncSetAttribute(gemm1_kernel,
            cudaFuncAttributeMaxDynamicSharedMemorySize, (int)sizeof(GemmSmem));
        cudaFuncSetAttribute(gemm2_kernel,
            cudaFuncAttributeMaxDynamicSharedMemorySize, (int)sizeof(GemmSmem));
        cudaFuncSetAttribute(attn_mma_kernel,
            cudaFuncAttributeMaxDynamicSharedMemorySize, (int)sizeof(AttnSmem));
        attr_set = true;
    }

    // 0) prep: x single fp16, weights hi/lo (QSC folded into q-cols)
    prep_kernel<<<1024, 256>>>(x, Wqkv, Wout);

    // 1) qkv = x @ Wqkv  (q,k,v single fp16)
    gemm1_kernel<<<dim3(3, 128), 256, sizeof(GemmSmem)>>>();

    // 2) warp-MMA flash attention (single-fp16 ao)
    attn_mma_kernel<<<BB * HH * 8, 256, sizeof(AttnSmem)>>>(mask, maps);

    // 3) out = ao @ Wout + bout
    gemm2_kernel<<<dim3(1, 128), 256, sizeof(GemmSmem)>>>(bout, out);
}